// round 1
// baseline (speedup 1.0000x reference)
#include <cuda_runtime.h>

// Reverse (suffix) cumulative sum along dim=1.
// x: (B=2048, N=32768) fp32. out[b, j] = sum_{k >= j} x[b, k].
//
// One CTA per row. 1024 threads/CTA, each thread owns 32 contiguous
// elements (8 x float4). Three-level suffix scan:
//   1. in-register suffix scan of the 32 owned elements
//   2. warp-level suffix scan of per-thread totals (shfl_down)
//   3. block-level suffix scan of per-warp totals (smem, warp 0)
// Single read + single write of global data => HBM roofline.

#define N_COLS 32768
#define THREADS 1024
#define PER_THREAD 32   // N_COLS / THREADS

__global__ __launch_bounds__(THREADS, 1)
void revcumsum_kernel(const float* __restrict__ x, float* __restrict__ out) {
    const long long base = (long long)blockIdx.x * N_COLS;
    const int t = threadIdx.x;
    const int lane = t & 31;
    const int wid = t >> 5;

    // ---- load 32 contiguous floats as 8 float4 ----
    const float4* __restrict__ xin =
        reinterpret_cast<const float4*>(x + base) + (t * (PER_THREAD / 4));
    float v[PER_THREAD];
    #pragma unroll
    for (int i = 0; i < PER_THREAD / 4; i++) {
        float4 r = xin[i];
        v[4 * i + 0] = r.x;
        v[4 * i + 1] = r.y;
        v[4 * i + 2] = r.z;
        v[4 * i + 3] = r.w;
    }

    // ---- per-thread suffix scan (inclusive) ----
    #pragma unroll
    for (int i = PER_THREAD - 2; i >= 0; i--) v[i] += v[i + 1];
    const float my_total = v[0];

    // ---- warp-level inclusive suffix scan of thread totals ----
    float incl = my_total;
    #pragma unroll
    for (int d = 1; d < 32; d <<= 1) {
        float tmp = __shfl_down_sync(0xFFFFFFFFu, incl, d);
        if (lane + d < 32) incl += tmp;
    }
    // incl = sum of totals of lanes >= my lane (within warp)

    __shared__ float warp_tot[32];
    __shared__ float warp_off[32];
    if (lane == 0) warp_tot[wid] = incl;  // full warp total
    __syncthreads();

    if (wid == 0) {
        float w = warp_tot[lane];
        float iw = w;
        #pragma unroll
        for (int d = 1; d < 32; d <<= 1) {
            float tmp = __shfl_down_sync(0xFFFFFFFFu, iw, d);
            if (lane + d < 32) iw += tmp;
        }
        warp_off[lane] = iw - w;  // exclusive suffix over warps (> my warp)
    }
    __syncthreads();

    // offset = (lanes after me in my warp) + (warps after mine)
    const float offset = (incl - my_total) + warp_off[wid];

    #pragma unroll
    for (int i = 0; i < PER_THREAD; i++) v[i] += offset;

    // ---- store 8 float4 ----
    float4* __restrict__ o =
        reinterpret_cast<float4*>(out + base) + (t * (PER_THREAD / 4));
    #pragma unroll
    for (int i = 0; i < PER_THREAD / 4; i++) {
        float4 r;
        r.x = v[4 * i + 0];
        r.y = v[4 * i + 1];
        r.z = v[4 * i + 2];
        r.w = v[4 * i + 3];
        o[i] = r;
    }
}

extern "C" void kernel_launch(void* const* d_in, const int* in_sizes, int n_in,
                              void* d_out, int out_size) {
    const float* x = (const float*)d_in[0];
    float* out = (float*)d_out;
    const int n = in_sizes[0];            // B * N
    const int rows = n / N_COLS;          // 2048
    revcumsum_kernel<<<rows, THREADS>>>(x, out);
}

// round 2
// speedup vs baseline: 1.7396x; 1.7396x over previous
#include <cuda_runtime.h>

// Reverse (suffix) cumulative sum along dim=1.
// x: (B=2048, N=32768) fp32. out[b, j] = sum_{k >= j} x[b, k].
//
// One CTA per row, 1024 threads. COALESCED register layout:
// warp w owns float4 tile [w*256, (w+1)*256); thread holds
// r[i] = tile[i*32 + lane] (i = 0..7) so every LDG.128 / STG.128 covers
// 4 contiguous 128B lines (full-width wavefronts), fixing the 8x L1
// wavefront inefficiency of the contiguous-per-thread layout.
//
// Suffix-scan on the interleaved layout:
//   1. suffix scan inside each float4
//   2. per-slot i: warp shfl suffix-scan over lanes -> excl_i, warp-slot total T_i
//   3. register suffix over i of T_i -> O_i
//   4. block scan over warp totals (smem)
// offset(i, lane) = warp_off + O_i + excl_i

#define N_COLS   32768
#define THREADS  1024
#define F4_PER_WARP 256   // 1024 floats per warp tile
#define SLOTS    8        // float4s per thread

__global__ __launch_bounds__(THREADS, 1)
void revcumsum_kernel(const float* __restrict__ x, float* __restrict__ out) {
    const long long base = (long long)blockIdx.x * N_COLS;
    const int t    = threadIdx.x;
    const int lane = t & 31;
    const int wid  = t >> 5;

    const float4* __restrict__ xin =
        reinterpret_cast<const float4*>(x + base) + wid * F4_PER_WARP + lane;

    // ---- coalesced load: slot i at float4 index i*32 + lane ----
    float4 r[SLOTS];
    #pragma unroll
    for (int i = 0; i < SLOTS; i++) r[i] = xin[i * 32];

    // ---- suffix scan inside each float4; s[i] = group sum ----
    float s[SLOTS];
    #pragma unroll
    for (int i = 0; i < SLOTS; i++) {
        r[i].z += r[i].w;
        r[i].y += r[i].z;
        r[i].x += r[i].y;
        s[i] = r[i].x;
    }

    // ---- per-slot warp suffix scan over lanes ----
    float excl[SLOTS];   // sum of s[i] for lanes > my lane
    float T[SLOTS];      // warp-wide total of slot i
    #pragma unroll
    for (int i = 0; i < SLOTS; i++) {
        float incl = s[i];
        #pragma unroll
        for (int d = 1; d < 32; d <<= 1) {
            float tmp = __shfl_down_sync(0xFFFFFFFFu, incl, d);
            if (lane + d < 32) incl += tmp;
        }
        excl[i] = incl - s[i];
        T[i]    = __shfl_sync(0xFFFFFFFFu, incl, 0);
    }

    // ---- register suffix over slots: O[i] = sum of T[i'] for i' > i ----
    float O[SLOTS];
    O[SLOTS - 1] = 0.0f;
    #pragma unroll
    for (int i = SLOTS - 2; i >= 0; i--) O[i] = O[i + 1] + T[i + 1];
    const float warp_total = O[0] + T[0];

    // ---- block suffix scan over warp totals ----
    __shared__ float warp_tot[32];
    __shared__ float warp_off[32];
    if (lane == 0) warp_tot[wid] = warp_total;
    __syncthreads();
    if (wid == 0) {
        float w  = warp_tot[lane];
        float iw = w;
        #pragma unroll
        for (int d = 1; d < 32; d <<= 1) {
            float tmp = __shfl_down_sync(0xFFFFFFFFu, iw, d);
            if (lane + d < 32) iw += tmp;
        }
        warp_off[lane] = iw - w;  // exclusive suffix over warps after mine
    }
    __syncthreads();
    const float woff = warp_off[wid];

    // ---- apply offsets, coalesced store ----
    float4* __restrict__ o =
        reinterpret_cast<float4*>(out + base) + wid * F4_PER_WARP + lane;
    #pragma unroll
    for (int i = 0; i < SLOTS; i++) {
        const float off = woff + O[i] + excl[i];
        float4 w;
        w.x = r[i].x + off;
        w.y = r[i].y + off;
        w.z = r[i].z + off;
        w.w = r[i].w + off;
        o[i * 32] = w;
    }
}

extern "C" void kernel_launch(void* const* d_in, const int* in_sizes, int n_in,
                              void* d_out, int out_size) {
    const float* x = (const float*)d_in[0];
    float* out = (float*)d_out;
    const int n = in_sizes[0];          // B * N
    const int rows = n / N_COLS;        // 2048
    revcumsum_kernel<<<rows, THREADS>>>(x, out);
}